// round 12
// baseline (speedup 1.0000x reference)
#include <cuda_runtime.h>
#include <cstdint>
#include <cstddef>

#define NPTS 4096
#define DIM  64
#define NBLK 128     // persistent blocks (<=148 SMs, 1 block/SM -> co-resident)
#define TPB  1024

// ---------------------------------------------------------------------------
// Scratch (allocation-free rule: __device__ globals)
// ---------------------------------------------------------------------------
__device__ float g_d2[(size_t)NPTS * NPTS];          // 64 MB f32, L2-resident
__device__ float g_len[NPTS];                        // MST edge lengths
__device__ unsigned long long g_bmin[NPTS * 32];     // per-(row,128col) mins
__device__ unsigned long long g_best[3][NPTS];       // triple-buffered comp keys
__device__ int          g_bar_cnt;
__device__ volatile int g_bar_gen;

static __device__ __forceinline__ float inf32() { return __int_as_float(0x7f800000); }
static __device__ __forceinline__ unsigned long long umin64(unsigned long long a,
                                                            unsigned long long b) {
    return a < b ? a : b;
}
// global key = (f32 d2 bits << 24) | (min(u,v)<<12) | max(u,v)
// globally unique; identical from both endpoints => only mutual 2-cycles.
static __device__ __forceinline__ unsigned long long mkkey(unsigned wbits,
                                                           unsigned a, unsigned b) {
    unsigned lo = min(a, b), hi = max(a, b);
    return ((unsigned long long)wbits << 24) | (lo << 12) | hi;
}
// local row key (w32<<32|j) of row c -> global canonical key
static __device__ __forceinline__ unsigned long long loc2key(unsigned long long ck,
                                                             unsigned c) {
    if (ck == ~0ull) return ~0ull;
    return mkkey((unsigned)(ck >> 32), c, (unsigned)(ck & 0xFFFFu));
}

static __device__ __forceinline__ void gridbar() {
    __syncthreads();
    if (threadIdx.x == 0) {
        __threadfence();
        int gen = g_bar_gen;
        if (atomicAdd(&g_bar_cnt, 1) == NBLK - 1) {
            g_bar_cnt = 0;
            __threadfence();
            g_bar_gen = gen + 1;
        } else {
            while (g_bar_gen == gen) { }
        }
        __threadfence();
    }
    __syncthreads();
}

// ---------------------------------------------------------------------------
// Kernel 1: d2 matrix (128x128 tile, 8x8/thread, packed f32x2 FMA) with
//  - in-kernel row norms (from smem tiles; no separate init kernel)
//  - fused per-(row, col-block) min epilogue -> g_bmin (w32<<32|j)
//  - housekeeping: by==0 blocks clear g_best; block (0,0) resets barrier
// ---------------------------------------------------------------------------
__global__ void k_d2(const float* __restrict__ p) {
    __shared__ float As[32][128];
    __shared__ float Bs[32][128];
    __shared__ float sAsq[128];
    __shared__ float sBsq[128];

    const int t  = threadIdx.x;          // 0..255
    const int tx = t & 15;
    const int ty = t >> 4;
    const int i0 = blockIdx.y * 128;
    const int j0 = blockIdx.x * 128;

    // housekeeping (ordered before k_mst by launch order)
    if (blockIdx.y == 0) {
        if (blockIdx.x == 0 && t == 0) { g_bar_cnt = 0; g_bar_gen = 0; }
        for (int e = t; e < 384; e += 256)
            g_best[e >> 7][blockIdx.x * 128 + (e & 127)] = ~0ull;
    }

    const int lr = t >> 1;
    const int lc = (t & 1) * 16;

    unsigned long long acc2[8][4];
#pragma unroll
    for (int m = 0; m < 8; m++)
#pragma unroll
        for (int n = 0; n < 4; n++) acc2[m][n] = 0ull;

    float nacc = 0.f;                    // per-thread row-norm partial

#pragma unroll
    for (int k0 = 0; k0 < DIM; k0 += 32) {
#pragma unroll
        for (int q = 0; q < 4; q++) {
            int c = lc + q * 4;
            float4 va = *(const float4*)(p + (size_t)(i0 + lr) * DIM + k0 + c);
            As[c + 0][lr] = va.x; As[c + 1][lr] = va.y;
            As[c + 2][lr] = va.z; As[c + 3][lr] = va.w;
            float4 vb = *(const float4*)(p + (size_t)(j0 + lr) * DIM + k0 + c);
            Bs[c + 0][lr] = vb.x; Bs[c + 1][lr] = vb.y;
            Bs[c + 2][lr] = vb.z; Bs[c + 3][lr] = vb.w;
        }
        __syncthreads();

        // row norms: threads 0-127 do A rows, 128-255 do B rows
        if (t < 128) {
#pragma unroll
            for (int k = 0; k < 32; k++) nacc = fmaf(As[k][t], As[k][t], nacc);
        } else {
#pragma unroll
            for (int k = 0; k < 32; k++) nacc = fmaf(Bs[k][t - 128], Bs[k][t - 128], nacc);
        }

#pragma unroll
        for (int k = 0; k < 32; k++) {
            uint4 a0 = *(const uint4*)&As[k][ty * 8];
            uint4 a1 = *(const uint4*)&As[k][ty * 8 + 4];
            unsigned au[8] = {a0.x, a0.y, a0.z, a0.w, a1.x, a1.y, a1.z, a1.w};
            ulonglong2 b0 = *(const ulonglong2*)&Bs[k][tx * 8];
            ulonglong2 b1 = *(const ulonglong2*)&Bs[k][tx * 8 + 4];
            unsigned long long bp[4] = {b0.x, b0.y, b1.x, b1.y};
#pragma unroll
            for (int m = 0; m < 8; m++) {
                unsigned long long ap;
                asm("mov.b64 %0, {%1, %1};" : "=l"(ap) : "r"(au[m]));
#pragma unroll
                for (int n = 0; n < 4; n++)
                    asm("fma.rn.f32x2 %0, %1, %2, %0;"
                        : "+l"(acc2[m][n]) : "l"(ap), "l"(bp[n]));
            }
        }
        __syncthreads();
    }

    if (t < 128) sAsq[t] = nacc; else sBsq[t - 128] = nacc;
    __syncthreads();

    float sqi[8], sqj[8];
#pragma unroll
    for (int m = 0; m < 8; m++) sqi[m] = sAsq[ty * 8 + m];
#pragma unroll
    for (int n = 0; n < 8; n++) sqj[n] = sBsq[tx * 8 + n];

#pragma unroll
    for (int m = 0; m < 8; m++) {
        const int row = i0 + ty * 8 + m;
        float o[8];
#pragma unroll
        for (int n = 0; n < 4; n++) {
            unsigned lo, hi;
            asm("mov.b64 {%0, %1}, %2;" : "=r"(lo), "=r"(hi) : "l"(acc2[m][n]));
            float d0 = __uint_as_float(lo), d1 = __uint_as_float(hi);
            o[2 * n + 0] = fmaxf(sqi[m] + sqj[2 * n + 0] - 2.f * d0, 0.f);
            o[2 * n + 1] = fmaxf(sqi[m] + sqj[2 * n + 1] - 2.f * d1, 0.f);
        }
        float* dst = g_d2 + (size_t)row * NPTS + j0 + tx * 8;
        *(float4*)(dst)     = *(float4*)(o);
        *(float4*)(dst + 4) = *(float4*)(o + 4);

        // fused per-(row, 128-col block) min (w<<32|j), diag excluded
        unsigned long long key = ~0ull;
#pragma unroll
        for (int n = 0; n < 8; n++) {
            unsigned jj = (unsigned)(j0 + tx * 8 + n);
            if (jj != (unsigned)row)
                key = umin64(key, ((unsigned long long)__float_as_uint(o[n]) << 32) | jj);
        }
#pragma unroll
        for (int s = 8; s > 0; s >>= 1)
            key = umin64(key, __shfl_down_sync(0xFFFFFFFFu, key, s, 16));
        if (tx == 0) g_bmin[row * 32 + blockIdx.x] = key;
    }
}

// ---------------------------------------------------------------------------
// Row selection via block-min bounds (exact == full-scan result).
// Returns best local key (w<<32|j) on lane 0.
// ---------------------------------------------------------------------------
static __device__ __forceinline__ unsigned long long select_row(
    int row, int lane, const unsigned short* comp) {
    const unsigned myc = comp[row];
    unsigned long long e = g_bmin[row * 32 + lane];
    unsigned ej = (unsigned)(e & 0xFFFFu);
    bool oc = comp[ej] != myc;                 // partner out-of-comp?
    unsigned long long cand = oc ? e : ~0ull;
#pragma unroll
    for (int s = 16; s > 0; s >>= 1)
        cand = umin64(cand, __shfl_xor_sync(0xFFFFFFFFu, cand, s));

    unsigned scanmask = __ballot_sync(0xFFFFFFFFu, !oc && e < cand);
    unsigned long long best = cand;
    while (scanmask) {
        int b = __ffs(scanmask) - 1;
        scanmask &= scanmask - 1;
        const float* r = g_d2 + (size_t)row * NPTS + b * 128;
#pragma unroll
        for (int s2 = 0; s2 < 4; s2++) {
            int jj = s2 * 32 + lane;
            if (comp[b * 128 + jj] != myc) {
                unsigned long long kk =
                    ((unsigned long long)__float_as_uint(r[jj]) << 32) |
                    (unsigned)(b * 128 + jj);
                best = umin64(best, kk);
            }
        }
    }
#pragma unroll
    for (int s = 16; s > 0; s >>= 1)
        best = umin64(best, __shfl_down_sync(0xFFFFFFFFu, best, s));
    return best;
}

// ---------------------------------------------------------------------------
// Kernel 2: persistent Boruvka + sort.
// Rounds 0-1: distributed selection (1 grid barrier each); blocks 1..127
// exit at the round-1 barrier. Rounds 2+: block 0 finishes solo (no
// barriers); g_best reads use __ldcg (L2-coherent). Hook over active
// components in smem; block 0 records lengths and sorts.
// ---------------------------------------------------------------------------
__global__ void __launch_bounds__(TPB, 1) k_mst(float* __restrict__ out) {
    __shared__ unsigned short comp[NPTS];     // 8 KB persistent labels
    __shared__ int par[NPTS];                 // 16 KB; reused as float sort buf
    __shared__ unsigned short act[2][NPTS];   // 16 KB ping-pong active comps
    __shared__ int s_na2;                     // next active count
    __shared__ int s_cnt;                     // block0 edge counter

    const int t    = threadIdx.x;
    const int wid  = t >> 5;
    const int lane = t & 31;
    const int row  = blockIdx.x * 32 + wid;

    for (int i = t; i < NPTS; i += TPB) {
        comp[i] = (unsigned short)i;
        act[0][i] = (unsigned short)i;
    }
    if (t == 0) s_cnt = 0;
    __syncthreads();

    int na = NPTS;

    for (int k = 0; k < 12; k++) {
        const int pp = k & 1;

        if (k < 2) {
            // ---- distributed selection: one row per warp ----
            unsigned long long best = select_row(row, lane, comp);
            if (lane == 0 && best != ~0ull)
                atomicMin(&g_best[k % 3][comp[row]], loc2key(best, (unsigned)row));
            gridbar();
            if (k == 1 && blockIdx.x != 0) return;   // hand off to block 0
        } else {
            // ---- solo selection: block 0 sweeps all rows ----
            for (int r = wid; r < NPTS; r += 32) {
                unsigned long long best = select_row(r, lane, comp);
                if (lane == 0 && best != ~0ull)
                    atomicMin(&g_best[k % 3][comp[r]], loc2key(best, (unsigned)r));
            }
            __syncthreads();
        }

        // ---- hook over ACTIVE components ----
        const unsigned long long* B = g_best[k % 3];
        for (int idx = t; idx < na; idx += TPB) { int c = act[pp][idx]; par[c] = c; }
        if (t == 0) s_na2 = 0;
        __syncthreads();

        for (int idx = t; idx < na; idx += TPB) {
            int c = act[pp][idx];
            unsigned long long key = __ldcg(&B[c]);
            bool isroot = false;
            if (key != ~0ull) {
                unsigned id = (unsigned)(key & 0xFFFFFFu);
                int u = (int)(id >> 12), v = (int)(id & 0xFFFu);
                int cu = comp[u], cv = comp[v];
                int other = (cu == c) ? cv : cu;
                bool mutual = (__ldcg(&B[other]) == key);
                if (!mutual)        par[c] = other;
                else if (c > other) par[c] = other;
                else                isroot = true;
                if (blockIdx.x == 0 && (!mutual || c < other)) {
                    int e = atomicAdd(&s_cnt, 1);
                    g_len[e] = sqrtf(__uint_as_float((unsigned)(key >> 24)));
                }
            } else {
                isroot = true;
            }
            if (isroot) {
                int pos = atomicAdd(&s_na2, 1);
                act[pp ^ 1][pos] = (unsigned short)c;
            }
        }
        __syncthreads();

        // pointer jumping over active list, early exit on convergence
        for (int it = 0; it < 12; it++) {
            int chg = 0;
            for (int idx = t; idx < na; idx += TPB) {
                int c = act[pp][idx];
                int p1 = par[c];
                int p2 = par[p1];
                if (p2 != p1) { par[c] = p2; chg = 1; }
            }
            if (!__syncthreads_or(chg)) break;
        }

        // relabel all vertices + clear buffer (k+2)%3
        for (int i = t; i < NPTS; i += TPB)
            comp[i] = (unsigned short)par[comp[i]];
        if (k == 0) {
            if (t < 32) g_best[2][blockIdx.x * 32 + t] = ~0ull;   // slice (all blocks)
        } else {
            for (int i = t; i < NPTS; i += TPB)                    // full (block 0)
                g_best[(k + 2) % 3][i] = ~0ull;
        }
        __syncthreads();

        na = s_na2;
        if (na <= 1 && k >= 1) break;
    }

    // ---- block 0: bitonic sort (pad one +inf), write output ----
    if (blockIdx.x != 0) return;
    __syncthreads();
    float* sh = (float*)par;
    for (int m = t; m < NPTS; m += TPB)
        sh[m] = (m < NPTS - 1) ? g_len[m] : inf32();
    __syncthreads();

    for (int kk = 2; kk <= NPTS; kk <<= 1) {
        for (int j = kk >> 1; j > 0; j >>= 1) {
#pragma unroll
            for (int tt = 0; tt < 2; tt++) {
                int u = t + tt * TPB;
                int i = ((u & ~(j - 1)) << 1) | (u & (j - 1));
                int l = i | j;
                float a = sh[i], c = sh[l];
                bool up = (i & kk) == 0;
                if ((a > c) == up) { sh[i] = c; sh[l] = a; }
            }
            __syncthreads();
        }
    }
    for (int m = t; m < NPTS - 1; m += TPB) out[m] = sh[m];
}

// ---------------------------------------------------------------------------
extern "C" void kernel_launch(void* const* d_in, const int* in_sizes, int n_in,
                              void* d_out, int out_size) {
    (void)in_sizes; (void)n_in; (void)out_size;
    const float* points = (const float*)d_in[0];
    float* out = (float*)d_out;

    k_d2<<<dim3(NPTS / 128, NPTS / 128), 256>>>(points);  // 32x32 x 256
    k_mst<<<NBLK, TPB>>>(out);
}

// round 13
// speedup vs baseline: 2.5686x; 2.5686x over previous
#include <cuda_runtime.h>
#include <cstdint>
#include <cstddef>

#define NPTS 4096
#define DIM  64
#define NBLK 128     // persistent blocks (<=148 SMs, 1 block/SM -> co-resident)
#define TPB  1024

// ---------------------------------------------------------------------------
// Scratch (allocation-free rule: __device__ globals)
// ---------------------------------------------------------------------------
__device__ float g_d2[(size_t)NPTS * NPTS];          // 64 MB f32, L2-resident
__device__ float g_len[NPTS];                        // MST edge lengths
__device__ unsigned long long g_bmin[NPTS * 32];     // per-(row,128col) mins
__device__ unsigned long long g_best[3][NPTS];       // triple-buffered comp keys
__device__ int          g_bar_cnt;
__device__ volatile int g_bar_gen;

static __device__ __forceinline__ float inf32() { return __int_as_float(0x7f800000); }
static __device__ __forceinline__ unsigned long long umin64(unsigned long long a,
                                                            unsigned long long b) {
    return a < b ? a : b;
}
// global key = (f32 d2 bits << 24) | (min(u,v)<<12) | max(u,v)
// globally unique; identical from both endpoints => only mutual 2-cycles.
static __device__ __forceinline__ unsigned long long mkkey(unsigned wbits,
                                                           unsigned a, unsigned b) {
    unsigned lo = min(a, b), hi = max(a, b);
    return ((unsigned long long)wbits << 24) | (lo << 12) | hi;
}
// local row key (w32<<32|j) of row c -> global canonical key
static __device__ __forceinline__ unsigned long long loc2key(unsigned long long ck,
                                                             unsigned c) {
    if (ck == ~0ull) return ~0ull;
    return mkkey((unsigned)(ck >> 32), c, (unsigned)(ck & 0xFFFFu));
}

static __device__ __forceinline__ void gridbar() {
    __syncthreads();
    if (threadIdx.x == 0) {
        __threadfence();
        int gen = g_bar_gen;
        if (atomicAdd(&g_bar_cnt, 1) == NBLK - 1) {
            g_bar_cnt = 0;
            __threadfence();
            g_bar_gen = gen + 1;
        } else {
            while (g_bar_gen == gen) { }
        }
        __threadfence();
    }
    __syncthreads();
}

// ---------------------------------------------------------------------------
// Kernel 1: d2 matrix (128x128 tile, 8x8/thread, packed f32x2 FMA) with
//  - in-kernel row norms (from smem tiles; no separate init kernel)
//  - fused per-(row, col-block) min epilogue -> g_bmin (w32<<32|j)
//  - housekeeping: by==0 blocks clear g_best; block (0,0) resets barrier
// ---------------------------------------------------------------------------
__global__ void k_d2(const float* __restrict__ p) {
    __shared__ float As[32][128];
    __shared__ float Bs[32][128];
    __shared__ float sAsq[128];
    __shared__ float sBsq[128];

    const int t  = threadIdx.x;          // 0..255
    const int tx = t & 15;
    const int ty = t >> 4;
    const int i0 = blockIdx.y * 128;
    const int j0 = blockIdx.x * 128;

    // housekeeping (ordered before k_mst by launch order)
    if (blockIdx.y == 0) {
        if (blockIdx.x == 0 && t == 0) { g_bar_cnt = 0; g_bar_gen = 0; }
        for (int e = t; e < 384; e += 256)
            g_best[e >> 7][blockIdx.x * 128 + (e & 127)] = ~0ull;
    }

    const int lr = t >> 1;
    const int lc = (t & 1) * 16;

    unsigned long long acc2[8][4];
#pragma unroll
    for (int m = 0; m < 8; m++)
#pragma unroll
        for (int n = 0; n < 4; n++) acc2[m][n] = 0ull;

    float nacc = 0.f;                    // per-thread row-norm partial

#pragma unroll
    for (int k0 = 0; k0 < DIM; k0 += 32) {
#pragma unroll
        for (int q = 0; q < 4; q++) {
            int c = lc + q * 4;
            float4 va = *(const float4*)(p + (size_t)(i0 + lr) * DIM + k0 + c);
            As[c + 0][lr] = va.x; As[c + 1][lr] = va.y;
            As[c + 2][lr] = va.z; As[c + 3][lr] = va.w;
            float4 vb = *(const float4*)(p + (size_t)(j0 + lr) * DIM + k0 + c);
            Bs[c + 0][lr] = vb.x; Bs[c + 1][lr] = vb.y;
            Bs[c + 2][lr] = vb.z; Bs[c + 3][lr] = vb.w;
        }
        __syncthreads();

        // row norms: threads 0-127 do A rows, 128-255 do B rows
        if (t < 128) {
#pragma unroll
            for (int k = 0; k < 32; k++) nacc = fmaf(As[k][t], As[k][t], nacc);
        } else {
#pragma unroll
            for (int k = 0; k < 32; k++) nacc = fmaf(Bs[k][t - 128], Bs[k][t - 128], nacc);
        }

#pragma unroll
        for (int k = 0; k < 32; k++) {
            uint4 a0 = *(const uint4*)&As[k][ty * 8];
            uint4 a1 = *(const uint4*)&As[k][ty * 8 + 4];
            unsigned au[8] = {a0.x, a0.y, a0.z, a0.w, a1.x, a1.y, a1.z, a1.w};
            ulonglong2 b0 = *(const ulonglong2*)&Bs[k][tx * 8];
            ulonglong2 b1 = *(const ulonglong2*)&Bs[k][tx * 8 + 4];
            unsigned long long bp[4] = {b0.x, b0.y, b1.x, b1.y};
#pragma unroll
            for (int m = 0; m < 8; m++) {
                unsigned long long ap;
                asm("mov.b64 %0, {%1, %1};" : "=l"(ap) : "r"(au[m]));
#pragma unroll
                for (int n = 0; n < 4; n++)
                    asm("fma.rn.f32x2 %0, %1, %2, %0;"
                        : "+l"(acc2[m][n]) : "l"(ap), "l"(bp[n]));
            }
        }
        __syncthreads();
    }

    if (t < 128) sAsq[t] = nacc; else sBsq[t - 128] = nacc;
    __syncthreads();

    float sqi[8], sqj[8];
#pragma unroll
    for (int m = 0; m < 8; m++) sqi[m] = sAsq[ty * 8 + m];
#pragma unroll
    for (int n = 0; n < 8; n++) sqj[n] = sBsq[tx * 8 + n];

#pragma unroll
    for (int m = 0; m < 8; m++) {
        const int row = i0 + ty * 8 + m;
        float o[8];
#pragma unroll
        for (int n = 0; n < 4; n++) {
            unsigned lo, hi;
            asm("mov.b64 {%0, %1}, %2;" : "=r"(lo), "=r"(hi) : "l"(acc2[m][n]));
            float d0 = __uint_as_float(lo), d1 = __uint_as_float(hi);
            o[2 * n + 0] = fmaxf(sqi[m] + sqj[2 * n + 0] - 2.f * d0, 0.f);
            o[2 * n + 1] = fmaxf(sqi[m] + sqj[2 * n + 1] - 2.f * d1, 0.f);
        }
        float* dst = g_d2 + (size_t)row * NPTS + j0 + tx * 8;
        *(float4*)(dst)     = *(float4*)(o);
        *(float4*)(dst + 4) = *(float4*)(o + 4);

        // fused per-(row, 128-col block) min (w<<32|j), diag excluded
        unsigned long long key = ~0ull;
#pragma unroll
        for (int n = 0; n < 8; n++) {
            unsigned jj = (unsigned)(j0 + tx * 8 + n);
            if (jj != (unsigned)row)
                key = umin64(key, ((unsigned long long)__float_as_uint(o[n]) << 32) | jj);
        }
#pragma unroll
        for (int s = 8; s > 0; s >>= 1)
            key = umin64(key, __shfl_down_sync(0xFFFFFFFFu, key, s, 16));
        if (tx == 0) g_bmin[row * 32 + blockIdx.x] = key;
    }
}

// ---------------------------------------------------------------------------
// Kernel 2: persistent Boruvka + sort. Selection per warp/row via block-min
// bounds (exact == full-scan selection); one grid barrier per round; hook
// over active components, all blocks redundantly in their own shared memory.
// ---------------------------------------------------------------------------
__global__ void __launch_bounds__(TPB, 1) k_mst(float* __restrict__ out) {
    __shared__ unsigned short comp[NPTS];     // 8 KB persistent labels
    __shared__ int par[NPTS];                 // 16 KB; reused as float sort buf
    __shared__ unsigned short act[2][NPTS];   // 16 KB ping-pong active comps
    __shared__ int s_na2;                     // next active count
    __shared__ int s_cnt;                     // block0 edge counter

    const int t    = threadIdx.x;
    const int wid  = t >> 5;
    const int lane = t & 31;
    const int row  = blockIdx.x * 32 + wid;

    for (int i = t; i < NPTS; i += TPB) {
        comp[i] = (unsigned short)i;
        act[0][i] = (unsigned short)i;
    }
    if (t == 0) s_cnt = 0;
    __syncthreads();

    int na = NPTS;

    for (int k = 0; k < 12; k++) {
        const int pp = k & 1;

        // ---- selection via block-min bounds ----
        {
            const unsigned myc = comp[row];
            unsigned long long e = g_bmin[row * 32 + lane];
            unsigned ej = (unsigned)(e & 0xFFFFu);
            bool oc = comp[ej] != myc;                 // partner out-of-comp?
            unsigned long long cand = oc ? e : ~0ull;
#pragma unroll
            for (int s = 16; s > 0; s >>= 1)
                cand = umin64(cand, __shfl_xor_sync(0xFFFFFFFFu, cand, s));

            unsigned scanmask = __ballot_sync(0xFFFFFFFFu, !oc && e < cand);
            unsigned long long best = cand;
            while (scanmask) {
                int b = __ffs(scanmask) - 1;
                scanmask &= scanmask - 1;
                const float* r = g_d2 + (size_t)row * NPTS + b * 128;
#pragma unroll
                for (int s2 = 0; s2 < 4; s2++) {
                    int jj = s2 * 32 + lane;
                    if (comp[b * 128 + jj] != myc) {
                        unsigned long long kk =
                            ((unsigned long long)__float_as_uint(r[jj]) << 32) |
                            (unsigned)(b * 128 + jj);
                        best = umin64(best, kk);
                    }
                }
            }
#pragma unroll
            for (int s = 16; s > 0; s >>= 1)
                best = umin64(best, __shfl_down_sync(0xFFFFFFFFu, best, s));
            if (lane == 0 && best != ~0ull)
                atomicMin(&g_best[k % 3][myc], loc2key(best, (unsigned)row));
        }
        gridbar();

        // ---- hook over ACTIVE components (all blocks, redundant) ----
        const unsigned long long* B = g_best[k % 3];
        for (int idx = t; idx < na; idx += TPB) { int c = act[pp][idx]; par[c] = c; }
        if (t == 0) s_na2 = 0;
        __syncthreads();

        for (int idx = t; idx < na; idx += TPB) {
            int c = act[pp][idx];
            unsigned long long key = B[c];
            bool isroot = false;
            if (key != ~0ull) {
                unsigned id = (unsigned)(key & 0xFFFFFFu);
                int u = (int)(id >> 12), v = (int)(id & 0xFFFu);
                int cu = comp[u], cv = comp[v];
                int other = (cu == c) ? cv : cu;
                bool mutual = (B[other] == key);
                if (!mutual)        par[c] = other;
                else if (c > other) par[c] = other;
                else                isroot = true;
                if (blockIdx.x == 0 && (!mutual || c < other)) {
                    int e = atomicAdd(&s_cnt, 1);
                    g_len[e] = sqrtf(__uint_as_float((unsigned)(key >> 24)));
                }
            } else {
                isroot = true;
            }
            if (isroot) {
                int pos = atomicAdd(&s_na2, 1);
                act[pp ^ 1][pos] = (unsigned short)c;
            }
        }
        __syncthreads();

        // pointer jumping over active list, early exit on convergence
        for (int it = 0; it < 12; it++) {
            int chg = 0;
            for (int idx = t; idx < na; idx += TPB) {
                int c = act[pp][idx];
                int p1 = par[c];
                int p2 = par[p1];
                if (p2 != p1) { par[c] = p2; chg = 1; }
            }
            if (!__syncthreads_or(chg)) break;
        }

        // relabel all vertices + clear this block's slice of buffer (k+2)%3
        for (int i = t; i < NPTS; i += TPB)
            comp[i] = (unsigned short)par[comp[i]];
        if (t < 32) g_best[(k + 2) % 3][blockIdx.x * 32 + t] = ~0ull;
        __syncthreads();

        na = s_na2;
        if (na <= 1) break;
    }

    // ---- block 0: bitonic sort (pad one +inf), write output ----
    if (blockIdx.x != 0) return;
    __syncthreads();
    float* sh = (float*)par;
    for (int m = t; m < NPTS; m += TPB)
        sh[m] = (m < NPTS - 1) ? g_len[m] : inf32();
    __syncthreads();

    for (int kk = 2; kk <= NPTS; kk <<= 1) {
        for (int j = kk >> 1; j > 0; j >>= 1) {
#pragma unroll
            for (int tt = 0; tt < 2; tt++) {
                int u = t + tt * TPB;
                int i = ((u & ~(j - 1)) << 1) | (u & (j - 1));
                int l = i | j;
                float a = sh[i], c = sh[l];
                bool up = (i & kk) == 0;
                if ((a > c) == up) { sh[i] = c; sh[l] = a; }
            }
            __syncthreads();
        }
    }
    for (int m = t; m < NPTS - 1; m += TPB) out[m] = sh[m];
}

// ---------------------------------------------------------------------------
extern "C" void kernel_launch(void* const* d_in, const int* in_sizes, int n_in,
                              void* d_out, int out_size) {
    (void)in_sizes; (void)n_in; (void)out_size;
    const float* points = (const float*)d_in[0];
    float* out = (float*)d_out;

    k_d2<<<dim3(NPTS / 128, NPTS / 128), 256>>>(points);  // 32x32 x 256
    k_mst<<<NBLK, TPB>>>(out);
}

// round 14
// speedup vs baseline: 3.9363x; 1.5325x over previous
#include <cuda_runtime.h>
#include <cstdint>
#include <cstddef>

#define NPTS 4096
#define DIM  64
#define NBLK 128     // persistent blocks (<=148 SMs, 1 block/SM -> co-resident)
#define TPB  1024

// ---------------------------------------------------------------------------
// Scratch (allocation-free rule: __device__ globals)
// ---------------------------------------------------------------------------
__device__ float g_sq[NPTS];
__device__ float g_d2[(size_t)NPTS * NPTS];          // 64 MB f32, L2-resident
__device__ float g_len[NPTS];                        // MST edge lengths
__device__ unsigned long long g_bmin[NPTS * 32];     // per-(row,128col) mins
__device__ unsigned long long g_best[3][NPTS];       // triple-buffered comp keys
__device__ int          g_bar_cnt;
__device__ volatile int g_bar_gen;

static __device__ __forceinline__ float inf32() { return __int_as_float(0x7f800000); }
static __device__ __forceinline__ unsigned long long umin64(unsigned long long a,
                                                            unsigned long long b) {
    return a < b ? a : b;
}
// global key = (f32 d2 bits << 24) | (min(u,v)<<12) | max(u,v)
// globally unique; identical from both endpoints => only mutual 2-cycles.
static __device__ __forceinline__ unsigned long long mkkey(unsigned wbits,
                                                           unsigned a, unsigned b) {
    unsigned lo = min(a, b), hi = max(a, b);
    return ((unsigned long long)wbits << 24) | (lo << 12) | hi;
}
// local row key (w32<<32|j) of row c -> global canonical key
static __device__ __forceinline__ unsigned long long loc2key(unsigned long long ck,
                                                             unsigned c) {
    if (ck == ~0ull) return ~0ull;
    return mkkey((unsigned)(ck >> 32), c, (unsigned)(ck & 0xFFFFu));
}

static __device__ __forceinline__ void gridbar() {
    __syncthreads();
    if (threadIdx.x == 0) {
        __threadfence();
        int gen = g_bar_gen;
        if (atomicAdd(&g_bar_cnt, 1) == NBLK - 1) {
            g_bar_cnt = 0;
            __threadfence();
            g_bar_gen = gen + 1;
        } else {
            while (g_bar_gen == gen) { }
        }
        __threadfence();
    }
    __syncthreads();
}

// ---------------------------------------------------------------------------
// Kernel 1: warp-per-row squared norms + clear best buffers + barrier reset
// ---------------------------------------------------------------------------
__global__ void k_init(const float* __restrict__ p) {
    const int t   = threadIdx.x;
    const int gt  = blockIdx.x * TPB + t;
    const int row = gt >> 5;
    const int ln  = gt & 31;

    if (gt == 0) { g_bar_cnt = 0; g_bar_gen = 0; }
    if (gt < 3 * NPTS) ((unsigned long long*)g_best)[gt] = ~0ull;

    float2 v = *(const float2*)(p + (size_t)row * DIM + ln * 2);
    float acc = fmaf(v.x, v.x, v.y * v.y);
#pragma unroll
    for (int s = 16; s > 0; s >>= 1)
        acc += __shfl_down_sync(0xFFFFFFFFu, acc, s);
    if (ln == 0) g_sq[row] = acc;
}

// ---------------------------------------------------------------------------
// Kernel 2: f32 d2 matrix (128x128 tile, 8x8/thread, packed f32x2 FMA) with
// fused per-(row, col-block) min epilogue -> g_bmin (w32<<32|j).
// ---------------------------------------------------------------------------
__global__ void k_d2(const float* __restrict__ p) {
    __shared__ float As[32][128];
    __shared__ float Bs[32][128];

    const int t  = threadIdx.x;          // 0..255
    const int tx = t & 15;
    const int ty = t >> 4;
    const int i0 = blockIdx.y * 128;
    const int j0 = blockIdx.x * 128;

    const int lr = t >> 1;
    const int lc = (t & 1) * 16;

    unsigned long long acc2[8][4];
#pragma unroll
    for (int m = 0; m < 8; m++)
#pragma unroll
        for (int n = 0; n < 4; n++) acc2[m][n] = 0ull;

#pragma unroll
    for (int k0 = 0; k0 < DIM; k0 += 32) {
#pragma unroll
        for (int q = 0; q < 4; q++) {
            int c = lc + q * 4;
            float4 va = *(const float4*)(p + (size_t)(i0 + lr) * DIM + k0 + c);
            As[c + 0][lr] = va.x; As[c + 1][lr] = va.y;
            As[c + 2][lr] = va.z; As[c + 3][lr] = va.w;
            float4 vb = *(const float4*)(p + (size_t)(j0 + lr) * DIM + k0 + c);
            Bs[c + 0][lr] = vb.x; Bs[c + 1][lr] = vb.y;
            Bs[c + 2][lr] = vb.z; Bs[c + 3][lr] = vb.w;
        }
        __syncthreads();

#pragma unroll
        for (int k = 0; k < 32; k++) {
            uint4 a0 = *(const uint4*)&As[k][ty * 8];
            uint4 a1 = *(const uint4*)&As[k][ty * 8 + 4];
            unsigned au[8] = {a0.x, a0.y, a0.z, a0.w, a1.x, a1.y, a1.z, a1.w};
            ulonglong2 b0 = *(const ulonglong2*)&Bs[k][tx * 8];
            ulonglong2 b1 = *(const ulonglong2*)&Bs[k][tx * 8 + 4];
            unsigned long long bp[4] = {b0.x, b0.y, b1.x, b1.y};
#pragma unroll
            for (int m = 0; m < 8; m++) {
                unsigned long long ap;
                asm("mov.b64 %0, {%1, %1};" : "=l"(ap) : "r"(au[m]));
#pragma unroll
                for (int n = 0; n < 4; n++)
                    asm("fma.rn.f32x2 %0, %1, %2, %0;"
                        : "+l"(acc2[m][n]) : "l"(ap), "l"(bp[n]));
            }
        }
        __syncthreads();
    }

    float sqi[8], sqj[8];
#pragma unroll
    for (int m = 0; m < 8; m++) sqi[m] = g_sq[i0 + ty * 8 + m];
#pragma unroll
    for (int n = 0; n < 8; n++) sqj[n] = g_sq[j0 + tx * 8 + n];

#pragma unroll
    for (int m = 0; m < 8; m++) {
        const int row = i0 + ty * 8 + m;
        float o[8];
#pragma unroll
        for (int n = 0; n < 4; n++) {
            unsigned lo, hi;
            asm("mov.b64 {%0, %1}, %2;" : "=r"(lo), "=r"(hi) : "l"(acc2[m][n]));
            float d0 = __uint_as_float(lo), d1 = __uint_as_float(hi);
            o[2 * n + 0] = fmaxf(sqi[m] + sqj[2 * n + 0] - 2.f * d0, 0.f);
            o[2 * n + 1] = fmaxf(sqi[m] + sqj[2 * n + 1] - 2.f * d1, 0.f);
        }
        float* dst = g_d2 + (size_t)row * NPTS + j0 + tx * 8;
        *(float4*)(dst)     = *(float4*)(o);
        *(float4*)(dst + 4) = *(float4*)(o + 4);

        // fused per-(row, 128-col block) min (w<<32|j), diag excluded
        unsigned long long key = ~0ull;
#pragma unroll
        for (int n = 0; n < 8; n++) {
            unsigned jj = (unsigned)(j0 + tx * 8 + n);
            if (jj != (unsigned)row)
                key = umin64(key, ((unsigned long long)__float_as_uint(o[n]) << 32) | jj);
        }
#pragma unroll
        for (int s = 8; s > 0; s >>= 1)
            key = umin64(key, __shfl_down_sync(0xFFFFFFFFu, key, s, 16));
        if (tx == 0) g_bmin[row * 32 + blockIdx.x] = key;
    }
}

// ---------------------------------------------------------------------------
// Kernel 3: persistent Boruvka + sort. Selection per warp/row via REGISTER-
// cached block-min entries (lane l owns col-block l): entries with out-of-
// comp partner are exact; stale entries are lower bounds; rescanned blocks
// write their refreshed min back into the owner lane's register (each block
// rescanned only when its stored partner gets absorbed). Exact selection.
// One grid barrier per round; hook over active components in smem.
// ---------------------------------------------------------------------------
__global__ void __launch_bounds__(TPB, 1) k_mst(float* __restrict__ out) {
    __shared__ unsigned short comp[NPTS];     // 8 KB persistent labels
    __shared__ int par[NPTS];                 // 16 KB; reused as float sort buf
    __shared__ unsigned short act[2][NPTS];   // 16 KB ping-pong active comps
    __shared__ int s_na2;                     // next active count
    __shared__ int s_cnt;                     // block0 edge counter

    const int t    = threadIdx.x;
    const int wid  = t >> 5;
    const int lane = t & 31;
    const int row  = blockIdx.x * 32 + wid;

    for (int i = t; i < NPTS; i += TPB) {
        comp[i] = (unsigned short)i;
        act[0][i] = (unsigned short)i;
    }
    if (t == 0) s_cnt = 0;
    __syncthreads();

    // lane l's register holds the cached min entry of col-block l for `row`
    unsigned long long e = g_bmin[row * 32 + lane];
    int na = NPTS;

    for (int k = 0; k < 12; k++) {
        const int pp = k & 1;

        // ---- selection via register-cached bounds ----
        {
            const unsigned myc = comp[row];
            unsigned ej = (unsigned)(e & 0xFFFu);        // 12-bit: always safe
            bool oc = comp[ej] != myc;                   // partner out-of-comp?
            unsigned long long cand = oc ? e : ~0ull;
#pragma unroll
            for (int s = 16; s > 0; s >>= 1)
                cand = umin64(cand, __shfl_xor_sync(0xFFFFFFFFu, cand, s));

            unsigned scanmask = __ballot_sync(0xFFFFFFFFu, !oc && e < cand);
            while (scanmask) {
                int b = __ffs(scanmask) - 1;
                scanmask &= scanmask - 1;
                unsigned long long eb = __shfl_sync(0xFFFFFFFFu, e, b);
                if (eb >= cand) continue;                // bound: can't beat cand
                const float* r = g_d2 + (size_t)row * NPTS + b * 128;
                unsigned long long m = ~0ull;
#pragma unroll
                for (int s2 = 0; s2 < 4; s2++) {
                    int jj = s2 * 32 + lane;
                    if (comp[b * 128 + jj] != myc) {
                        unsigned long long kk =
                            ((unsigned long long)__float_as_uint(r[jj]) << 32) |
                            (unsigned)(b * 128 + jj);
                        m = umin64(m, kk);
                    }
                }
#pragma unroll
                for (int s = 16; s > 0; s >>= 1)
                    m = umin64(m, __shfl_xor_sync(0xFFFFFFFFu, m, s));
                if (lane == b) e = m;                    // write-back (exact now)
                cand = umin64(cand, m);                  // tighten bound
            }
            if (lane == 0 && cand != ~0ull)
                atomicMin(&g_best[k % 3][myc], loc2key(cand, (unsigned)row));
        }
        gridbar();

        // ---- hook over ACTIVE components (all blocks, redundant) ----
        const unsigned long long* B = g_best[k % 3];
        for (int idx = t; idx < na; idx += TPB) { int c = act[pp][idx]; par[c] = c; }
        if (t == 0) s_na2 = 0;
        __syncthreads();

        for (int idx = t; idx < na; idx += TPB) {
            int c = act[pp][idx];
            unsigned long long key = B[c];
            bool isroot = false;
            if (key != ~0ull) {
                unsigned id = (unsigned)(key & 0xFFFFFFu);
                int u = (int)(id >> 12), v = (int)(id & 0xFFFu);
                int cu = comp[u], cv = comp[v];
                int other = (cu == c) ? cv : cu;
                bool mutual = (B[other] == key);
                if (!mutual)        par[c] = other;
                else if (c > other) par[c] = other;
                else                isroot = true;
                if (blockIdx.x == 0 && (!mutual || c < other)) {
                    int e2 = atomicAdd(&s_cnt, 1);
                    g_len[e2] = sqrtf(__uint_as_float((unsigned)(key >> 24)));
                }
            } else {
                isroot = true;
            }
            if (isroot) {
                int pos = atomicAdd(&s_na2, 1);
                act[pp ^ 1][pos] = (unsigned short)c;
            }
        }
        __syncthreads();

        // pointer jumping over active list, early exit on convergence
        for (int it = 0; it < 12; it++) {
            int chg = 0;
            for (int idx = t; idx < na; idx += TPB) {
                int c = act[pp][idx];
                int p1 = par[c];
                int p2 = par[p1];
                if (p2 != p1) { par[c] = p2; chg = 1; }
            }
            if (!__syncthreads_or(chg)) break;
        }

        // relabel all vertices + clear this block's slice of buffer (k+2)%3
        for (int i = t; i < NPTS; i += TPB)
            comp[i] = (unsigned short)par[comp[i]];
        if (t < 32) g_best[(k + 2) % 3][blockIdx.x * 32 + t] = ~0ull;
        __syncthreads();

        na = s_na2;
        if (na <= 1) break;
    }

    // ---- block 0: bitonic sort (pad one +inf), write output ----
    if (blockIdx.x != 0) return;
    __syncthreads();
    float* sh = (float*)par;
    for (int m = t; m < NPTS; m += TPB)
        sh[m] = (m < NPTS - 1) ? g_len[m] : inf32();
    __syncthreads();

    for (int kk = 2; kk <= NPTS; kk <<= 1) {
        for (int j = kk >> 1; j > 0; j >>= 1) {
#pragma unroll
            for (int tt = 0; tt < 2; tt++) {
                int u = t + tt * TPB;
                int i = ((u & ~(j - 1)) << 1) | (u & (j - 1));
                int l = i | j;
                float a = sh[i], c = sh[l];
                bool up = (i & kk) == 0;
                if ((a > c) == up) { sh[i] = c; sh[l] = a; }
            }
            __syncthreads();
        }
    }
    for (int m = t; m < NPTS - 1; m += TPB) out[m] = sh[m];
}

// ---------------------------------------------------------------------------
extern "C" void kernel_launch(void* const* d_in, const int* in_sizes, int n_in,
                              void* d_out, int out_size) {
    (void)in_sizes; (void)n_in; (void)out_size;
    const float* points = (const float*)d_in[0];
    float* out = (float*)d_out;

    k_init<<<NPTS * 32 / TPB, TPB>>>(points);            // 128 x 1024
    k_d2<<<dim3(NPTS / 128, NPTS / 128), 256>>>(points); // 32x32 x 256
    k_mst<<<NBLK, TPB>>>(out);
}